// round 10
// baseline (speedup 1.0000x reference)
#include <cuda_runtime.h>
#include <cuda_bf16.h>
#include <math.h>
#include <stdint.h>

// ---------------- problem constants ----------------
#define NB      512
#define ND      32
#define NLAT    128
#define NSMALL  500
#define NMID    2000
#define NITEMS  50000
#define NUSERS  2000
#define TWOK    40
#define KOUT    20
#define KPAD    2048
#define NCAND   4096          // per-row candidate cap (hard worst-case ~1600)
#define NBLK    391           // ceil(50000/128) item blocks
#define BCAP    16384         // bucket capacity per item block (4x worst estimate)
#define MYCAP   64            // BCAP / 256 threads

// expected element counts
#define SZ_X      (NB*ND)
#define SZ_MASK   (NB*NITEMS)
#define SZ_WPRIOR (ND*NLAT)
#define SZ_WSDEC  (NLAT*NSMALL)
#define SZ_WMDEC  (NLAT*NMID)
#define SZ_WMAP   (ND*3)
#define SZ_R      (NUSERS*NITEMS)
#define SZ_P      (NUSERS*ND)
#define SZ_TMAP   (NSMALL)
#define SZ_MMAP   (NMID)

// ---------------- device scratch ----------------
__device__ float g_sim[NB * NUSERS];
__device__ __nv_bfloat16 g_simh[NB * KPAD];
__device__ float g_ps [NB * 512];
__device__ float g_pm [NB * 2048];
__device__ float g_probs[NB * 4];
__device__ float g_kp [(size_t)NB * NITEMS];     // approx knn preds
__device__ int   g_clist[NB * NCAND];            // candidate item ids per row
__device__ float g_cex  [NB * NCAND];            // exact fp32 values per candidate
__device__ int   g_cn   [NB];                    // candidate counts
__device__ int   g_bucket[NBLK * BCAP];          // (row<<16)|slot per item block
__device__ int   g_bcnt [NBLK];
__device__ float g_cval[NB * 64];                // exact knn top-40 values
__device__ int   g_cidx[NB * 64];
__device__ int   g_ccnt[NB];

// ---------------- warp-mma helpers ----------------
__device__ __forceinline__ uint32_t smem_u32(const void* p) {
    uint32_t a;
    asm("{ .reg .u64 t; cvta.to.shared.u64 t, %1; cvt.u32.u64 %0, t; }" : "=r"(a) : "l"(p));
    return a;
}
__device__ __forceinline__ void ldsm_x4(uint32_t& r0, uint32_t& r1, uint32_t& r2, uint32_t& r3,
                                        uint32_t addr) {
    asm volatile("ldmatrix.sync.aligned.m8n8.x4.shared.b16 {%0,%1,%2,%3}, [%4];"
        : "=r"(r0), "=r"(r1), "=r"(r2), "=r"(r3) : "r"(addr));
}
__device__ __forceinline__ void ldsm_x4_t(uint32_t& r0, uint32_t& r1, uint32_t& r2, uint32_t& r3,
                                          uint32_t addr) {
    asm volatile("ldmatrix.sync.aligned.m8n8.x4.trans.shared.b16 {%0,%1,%2,%3}, [%4];"
        : "=r"(r0), "=r"(r1), "=r"(r2), "=r"(r3) : "r"(addr));
}
__device__ __forceinline__ void mma_bf16(float* c, const uint32_t* a, const uint32_t* b) {
    asm volatile(
        "mma.sync.aligned.m16n8k16.row.col.f32.bf16.bf16.f32 "
        "{%0,%1,%2,%3}, {%4,%5,%6,%7}, {%8,%9}, {%0,%1,%2,%3};"
        : "+f"(c[0]), "+f"(c[1]), "+f"(c[2]), "+f"(c[3])
        : "r"(a[0]), "r"(a[1]), "r"(a[2]), "r"(a[3]), "r"(b[0]), "r"(b[1]));
}

// =====================================================================
// Kernel 1: per-row small math (+ bf16 sim; zero bucket counters)
// =====================================================================
__global__ __launch_bounds__(256)
void prep_kernel(const float* __restrict__ X, const float* __restrict__ mask,
                 const float* __restrict__ Wsp, const float* __restrict__ Wsd,
                 const float* __restrict__ Wmp, const float* __restrict__ Wmd,
                 const float* __restrict__ Wmap, const float* __restrict__ P,
                 const int* __restrict__ top_map, const int* __restrict__ mid_map)
{
    int row = blockIdx.x;
    int tid = threadIdx.x;

    if (tid == 0 && row < NBLK) g_bcnt[row] = 0;

    __shared__ float sx[ND];
    __shared__ float hs[NLAT];
    __shared__ float hm[NLAT];
    __shared__ float lg[NUSERS];
    __shared__ float red[256];

    if (tid < ND) sx[tid] = X[row * ND + tid];
    __syncthreads();

    if (tid < NLAT) {
        float a = 0.f;
        #pragma unroll
        for (int d = 0; d < ND; d++) a += sx[d] * Wsp[d * NLAT + tid];
        hs[tid] = a;
    } else {
        int t = tid - NLAT;
        float a = 0.f;
        #pragma unroll
        for (int d = 0; d < ND; d++) a += sx[d] * Wmp[d * NLAT + t];
        hm[t] = a;
    }
    __syncthreads();

    for (int i = tid; i < NSMALL; i += 256) {
        float a = 0.f;
        #pragma unroll 8
        for (int l = 0; l < NLAT; l++) a += hs[l] * Wsd[l * NSMALL + i];
        a *= mask[(size_t)row * NITEMS + top_map[i]];
        g_ps[row * 512 + i] = a;
    }
    for (int i = tid; i < NMID; i += 256) {
        float a = 0.f;
        #pragma unroll 8
        for (int l = 0; l < NLAT; l++) a += hm[l] * Wmd[l * NMID + i];
        a *= mask[(size_t)row * NITEMS + mid_map[i]];
        g_pm[row * 2048 + i] = a;
    }

    if (tid == 0) {
        float l0 = 0.f, l1 = 0.f, l2 = 0.f;
        for (int d = 0; d < ND; d++) {
            float x = sx[d];
            l0 += x * Wmap[d * 3 + 0];
            l1 += x * Wmap[d * 3 + 1];
            l2 += x * Wmap[d * 3 + 2];
        }
        float m  = fmaxf(l0, fmaxf(l1, l2));
        float e0 = expf(l0 - m), e1 = expf(l1 - m), e2 = expf(l2 - m);
        float z  = e0 + e1 + e2;
        g_probs[row * 4 + 0] = e0 / z;
        g_probs[row * 4 + 1] = e1 / z;
        g_probs[row * 4 + 2] = e2 / z;
    }

    const float inv_scale = 1.0f / sqrtf((float)ND);
    for (int u = tid; u < NUSERS; u += 256) {
        float a = 0.f;
        #pragma unroll
        for (int d = 0; d < ND; d++) a += sx[d] * P[u * ND + d];
        lg[u] = a * inv_scale;
    }
    __syncthreads();

    float lm = -INFINITY;
    for (int u = tid; u < NUSERS; u += 256) lm = fmaxf(lm, lg[u]);
    red[tid] = lm; __syncthreads();
    for (int s = 128; s > 0; s >>= 1) { if (tid < s) red[tid] = fmaxf(red[tid], red[tid + s]); __syncthreads(); }
    float mx = red[0];
    __syncthreads();

    float ls = 0.f;
    for (int u = tid; u < NUSERS; u += 256) { float e = expf(lg[u] - mx); lg[u] = e; ls += e; }
    red[tid] = ls; __syncthreads();
    for (int s = 128; s > 0; s >>= 1) { if (tid < s) red[tid] += red[tid + s]; __syncthreads(); }
    float z = red[0];

    float invz = 1.0f / z;
    for (int u = tid; u < KPAD; u += 256) {
        float s = 0.f;
        if (u < NUSERS) { s = lg[u] * invz; g_sim[row * NUSERS + u] = s; }
        g_simh[row * KPAD + u] = __float2bfloat16(s);
    }
}

// =====================================================================
// Kernel 2: bf16 mma.sync GEMM (approx; E_rel <= 2^-7 + small)
// =====================================================================
#define LDA 40
#define LDB 136

__global__ __launch_bounds__(256, 2)
void gemm_mma_kernel(const float* __restrict__ R)
{
    __shared__ __align__(16) __nv_bfloat16 sA[128 * LDA];
    __shared__ __align__(16) __nv_bfloat16 sB[32 * LDB];

    int tid  = threadIdx.x;
    int wid  = tid >> 5;
    int lane = tid & 31;
    int m0 = blockIdx.x * 128;
    int n0 = blockIdx.y * 128;

    int warp_m = (wid >> 2) * 64;
    int warp_n = (wid & 3) * 32;

    float acc[4][4][4];
    #pragma unroll
    for (int i = 0; i < 4; i++)
        #pragma unroll
        for (int j = 0; j < 4; j++)
            #pragma unroll
            for (int q = 0; q < 4; q++) acc[i][j][q] = 0.f;

    uint32_t sA_base = smem_u32(sA);
    uint32_t sB_base = smem_u32(sB);

    for (int kt = 0; kt < KPAD; kt += 32) {
        #pragma unroll
        for (int j = 0; j < 2; j++) {
            int u = tid + j * 256;
            int m = u >> 2;
            int c = u & 3;
            *(uint4*)&sA[m * LDA + c * 8] =
                *(const uint4*)&g_simh[(size_t)(m0 + m) * KPAD + kt + c * 8];
        }
        #pragma unroll
        for (int j = 0; j < 4; j++) {
            int u  = tid + j * 256;
            int kk = u >> 5;
            int n4 = (u & 31) << 2;
            int kg = kt + kk;
            int gn = n0 + n4;
            float4 v = make_float4(0.f, 0.f, 0.f, 0.f);
            if (kg < NUSERS && gn < NITEMS)
                v = *(const float4*)&R[(size_t)kg * NITEMS + gn];
            __nv_bfloat162 p0, p1;
            p0.x = __float2bfloat16(v.x); p0.y = __float2bfloat16(v.y);
            p1.x = __float2bfloat16(v.z); p1.y = __float2bfloat16(v.w);
            *(__nv_bfloat162*)&sB[kk * LDB + n4]     = p0;
            *(__nv_bfloat162*)&sB[kk * LDB + n4 + 2] = p1;
        }
        __syncthreads();

        #pragma unroll
        for (int ks = 0; ks < 2; ks++) {
            uint32_t a[4][4];
            #pragma unroll
            for (int mt = 0; mt < 4; mt++) {
                int row = warp_m + mt * 16 + (lane & 15);
                int col = ks * 16 + (lane >> 4) * 8;
                ldsm_x4(a[mt][0], a[mt][1], a[mt][2], a[mt][3],
                        sA_base + (uint32_t)(row * LDA + col) * 2u);
            }
            uint32_t b[4][2];
            #pragma unroll
            for (int np = 0; np < 2; np++) {
                int row = ks * 16 + (lane & 15);
                int col = warp_n + np * 16 + (lane >> 4) * 8;
                uint32_t r0, r1, r2, r3;
                ldsm_x4_t(r0, r1, r2, r3,
                          sB_base + (uint32_t)(row * LDB + col) * 2u);
                b[np * 2][0] = r0; b[np * 2][1] = r1;
                b[np * 2 + 1][0] = r2; b[np * 2 + 1][1] = r3;
            }
            #pragma unroll
            for (int mt = 0; mt < 4; mt++)
                #pragma unroll
                for (int nt = 0; nt < 4; nt++)
                    mma_bf16(acc[mt][nt], a[mt], b[nt]);
        }
        __syncthreads();
    }

    int r0 = m0 + warp_m + (lane >> 2);
    int c0 = n0 + warp_n + (lane & 3) * 2;
    #pragma unroll
    for (int mt = 0; mt < 4; mt++) {
        #pragma unroll
        for (int nt = 0; nt < 4; nt++) {
            int col = c0 + nt * 8;
            if (col < NITEMS) {
                int ra = r0 + mt * 16;
                float2 lo = make_float2(acc[mt][nt][0], acc[mt][nt][1]);
                float2 hi = make_float2(acc[mt][nt][2], acc[mt][nt][3]);
                *(float2*)&g_kp[(size_t)ra * NITEMS + col]       = lo;
                *(float2*)&g_kp[(size_t)(ra + 8) * NITEMS + col] = hi;
            }
        }
    }
}

// =====================================================================
// radix-select helper
// =====================================================================
__device__ unsigned radix_pivot(const float* __restrict__ sv, int n, int target,
                                int* hist, int* scratch, int tid, int nthr)
{
    unsigned prefix = 0u, highmask = 0u;
    for (int shift = 24; shift >= 0; shift -= 8) {
        for (int i = tid; i < 256; i += nthr) hist[i] = 0;
        __syncthreads();
        for (int i = tid; i < n; i += nthr) {
            float v = sv[i];
            unsigned u = (v > 0.f) ? __float_as_uint(v) : 0u;
            if ((u & highmask) == prefix)
                atomicAdd(&hist[(u >> shift) & 255], 1);
        }
        __syncthreads();
        if (tid == 0) {
            int cum = 0, d = 255;
            for (; d >= 0; --d) { cum += hist[d]; if (cum >= target) break; }
            if (d < 0) d = 0;
            scratch[0] = d;
            scratch[1] = target - (cum - hist[d]);
        }
        __syncthreads();
        prefix   |= ((unsigned)scratch[0]) << shift;
        highmask |= 0xFFu << shift;
        target    = scratch[1];
        __syncthreads();
    }
    return prefix;
}

// =====================================================================
// Kernel 3: banded candidate selection (provable band) + bucketing
// =====================================================================
__global__ __launch_bounds__(256)
void knn_select_kernel()
{
    int row = blockIdx.x;
    int tid = threadIdx.x;
    __shared__ int hist[256];
    __shared__ int scratch[2];
    __shared__ int s_cnt;

    const float* rowp = g_kp + (size_t)row * NITEMS;
    unsigned pivot = radix_pivot(rowp, NITEMS, TWOK, hist, scratch, tid, 256);
    float pv = __uint_as_float(pivot);
    float thresh = pv - pv * 0.015625f - 5e-4f;

    if (tid == 0) s_cnt = 0;
    __syncthreads();
    for (int i = tid; i < NITEMS; i += 256) {
        float v = rowp[i];
        if (v > 0.f && v >= thresh) {
            int p = atomicAdd(&s_cnt, 1);
            if (p < NCAND) {
                g_clist[row * NCAND + p] = i;
                int b = i >> 7;
                int q = atomicAdd(&g_bcnt[b], 1);
                if (q < BCAP) g_bucket[b * BCAP + q] = (row << 16) | p;
            }
        }
    }
    __syncthreads();
    if (tid == 0) g_cn[row] = min(s_cnt, NCAND);
}

// =====================================================================
// Kernel 4: exact fp32 refinement via coalesced sweep of R.
//   CRITICAL: each candidate's value is ONE fma chain over k = 0..1999
//   ascending — bitwise identical to the R4 SGEMM arithmetic that passed
//   with rel_err 0.0 (same operands g_sim / R, same op order, fmaf).
// =====================================================================
#define TK  50
#define TLD 132

__global__ __launch_bounds__(256)
void refine_kernel(const float* __restrict__ R)
{
    __shared__ float tile[TK * TLD];

    int b   = blockIdx.x;
    int tid = threadIdx.x;
    int i0  = b * 128;

    int nb = min(g_bcnt[b], BCAP);

    int   myRow[MYCAP], mySlot[MYCAP], myIo[MYCAP];
    float myAcc[MYCAP];
    int myN = 0;
    for (int e = tid; e < nb && myN < MYCAP; e += 256) {
        int ent  = g_bucket[b * BCAP + e];
        int row  = ent >> 16;
        int slot = ent & 0xFFFF;
        myRow[myN]  = row;
        mySlot[myN] = slot;
        myIo[myN]   = g_clist[row * NCAND + slot] - i0;
        myAcc[myN]  = 0.f;
        myN++;
    }

    for (int c = 0; c < NUSERS / TK; c++) {
        int k0 = c * TK;
        __syncthreads();
        for (int t = tid; t < TK * 128; t += 256) {
            int kk = t >> 7;
            int ii = t & 127;
            int gi = i0 + ii;
            tile[kk * TLD + ii] = (gi < NITEMS) ? R[(size_t)(k0 + kk) * NITEMS + gi] : 0.f;
        }
        __syncthreads();
        for (int j = 0; j < myN; j++) {
            const float* sp = &g_sim[myRow[j] * NUSERS + k0];
            int io = myIo[j];
            float acc = myAcc[j];
            #pragma unroll 10
            for (int kk = 0; kk < TK; kk++)
                acc = fmaf(sp[kk], tile[kk * TLD + io], acc);   // single chain, k ascending
            myAcc[j] = acc;
        }
    }

    for (int j = 0; j < myN; j++)
        g_cex[myRow[j] * NCAND + mySlot[j]] = myAcc[j];
}

// =====================================================================
// Kernel 5: exact per-row top-40 from refined values
// =====================================================================
__global__ __launch_bounds__(256)
void rank_kernel()
{
    int row = blockIdx.x;
    int tid = threadIdx.x;
    __shared__ unsigned long long keys[NCAND];   // 32 KB

    int c = g_cn[row];
    for (int j = tid; j < c; j += 256) {
        float v  = g_cex[row * NCAND + j];
        int   id = g_clist[row * NCAND + j];
        keys[j] = (((unsigned long long)__float_as_uint(v)) << 32)
                  | (unsigned)(0xFFFFFFFFu - (unsigned)id);
    }
    __syncthreads();
    for (int j = tid; j < c; j += 256) {
        unsigned long long kj = keys[j];
        int rank = 0;
        for (int o = 0; o < c; o++) rank += (keys[o] > kj);
        if (rank < TWOK) {
            g_cval[row * 64 + rank] = __uint_as_float((unsigned)(kj >> 32));
            g_cidx[row * 64 + rank] = (int)(0xFFFFFFFFu - (unsigned)(kj & 0xFFFFFFFFu));
        }
    }
    if (tid == 0) g_ccnt[row] = min(c, TWOK);
}

// =====================================================================
// Kernel 6: per-row branch selection + fusion + final top-20 (ordered)
// =====================================================================
__global__ __launch_bounds__(256)
void fuse_kernel(const int* __restrict__ top_map, const int* __restrict__ mid_map,
                 float* __restrict__ out)
{
    int row = blockIdx.x;
    int tid = threadIdx.x;

    __shared__ float sv[2048];
    __shared__ int   hist[256];
    __shared__ int   scratch[2];
    __shared__ int   s_npos, s_ncand, s_base;
    __shared__ int   cIdx[192];
    __shared__ float cVal[192];
    __shared__ unsigned long long keys[192];

    float p0 = g_probs[row * 4 + 0];
    float p1 = g_probs[row * 4 + 1];
    float p2 = g_probs[row * 4 + 2];

    if (tid == 0) s_ncand = 0;

    // ---------- small branch ----------
    for (int i = tid; i < NSMALL; i += 256) sv[i] = g_ps[row * 512 + i];
    if (tid == 0) s_npos = 0;
    __syncthreads();
    {
        int cp = 0;
        for (int i = tid; i < NSMALL; i += 256) cp += (sv[i] > 0.f);
        atomicAdd(&s_npos, cp);
    }
    __syncthreads();
    {
        int npos = s_npos;
        int tk = min(TWOK, npos);
        unsigned pivot = 1u;
        if (npos > TWOK) pivot = radix_pivot(sv, NSMALL, tk, hist, scratch, tid, 256);
        __syncthreads();
        if (tk > 0) {
            for (int i = tid; i < NSMALL; i += 256) {
                float v = sv[i];
                if (v > 0.f && __float_as_uint(v) >= pivot) {
                    int p = atomicAdd(&s_ncand, 1);
                    if (p < 192) { cIdx[p] = top_map[i]; cVal[p] = v * p0; }
                }
            }
        }
    }
    __syncthreads();

    // ---------- mid branch ----------
    for (int i = tid; i < NMID; i += 256) sv[i] = g_pm[row * 2048 + i];
    if (tid == 0) s_npos = 0;
    __syncthreads();
    {
        int cp = 0;
        for (int i = tid; i < NMID; i += 256) cp += (sv[i] > 0.f);
        atomicAdd(&s_npos, cp);
    }
    __syncthreads();
    {
        int npos = s_npos;
        int tk = min(TWOK, npos);
        unsigned pivot = 1u;
        if (npos > TWOK) pivot = radix_pivot(sv, NMID, tk, hist, scratch, tid, 256);
        __syncthreads();
        if (tk > 0) {
            for (int i = tid; i < NMID; i += 256) {
                float v = sv[i];
                if (v > 0.f && __float_as_uint(v) >= pivot) {
                    int p = atomicAdd(&s_ncand, 1);
                    if (p < 192) { cIdx[p] = mid_map[i]; cVal[p] = v * p1; }
                }
            }
        }
    }
    __syncthreads();
    if (tid == 0) s_base = min(s_ncand, 192);
    __syncthreads();
    int base = s_base;

    // ---------- knn branch (accumulate on index collisions) ----------
    int kc = g_ccnt[row];
    for (int j = tid; j < kc; j += 256) {
        int   idx = g_cidx[row * 64 + j];
        float v   = g_cval[row * 64 + j] * p2;
        int found = -1;
        for (int q = 0; q < base; q++) {
            if (cIdx[q] == idx) { found = q; break; }
        }
        if (found >= 0) {
            cVal[found] += v;
        } else {
            int p = atomicAdd(&s_ncand, 1);
            if (p < 192) { cIdx[p] = idx; cVal[p] = v; }
        }
    }
    __syncthreads();

    // ---------- final top-20 with jax tie rule ----------
    int n = min(s_ncand, 192);
    for (int c2 = tid; c2 < n; c2 += 256) {
        keys[c2] = (((unsigned long long)__float_as_uint(cVal[c2])) << 32)
                   | (unsigned)(0xFFFFFFFFu - (unsigned)cIdx[c2]);
    }
    __syncthreads();
    for (int c2 = tid; c2 < n; c2 += 256) {
        unsigned long long kcv = keys[c2];
        int rank = 0;
        for (int o = 0; o < n; o++) rank += (keys[o] > kcv);
        if (rank < KOUT) out[row * KOUT + rank] = (float)cIdx[c2];
    }
    __syncthreads();

    if (tid == 0 && n < KOUT) {
        int fill = n;
        for (int idx = 0; idx < NITEMS && fill < KOUT; idx++) {
            bool used = false;
            for (int q = 0; q < n; q++) if (cIdx[q] == idx) { used = true; break; }
            if (!used) out[row * KOUT + fill++] = (float)idx;
        }
    }
}

// =====================================================================
// launch
// =====================================================================
extern "C" void kernel_launch(void* const* d_in, const int* in_sizes, int n_in,
                              void* d_out, int out_size)
{
    int iX=0, iMask=1, iWsp=2, iWsd=3, iWmp=4, iWmd=5, iWmap=6, iR=7, iP=8, iTmap=9, iMmap=10;

    if (in_sizes[0] == SZ_X && in_sizes[1] == SZ_MASK && in_sizes[7] == SZ_R) {
        // dict order
    } else if (in_sizes[0] == SZ_WMAP && in_sizes[1] == SZ_WMDEC) {
        iWmap = 0; iWmd = 1; iWmp = 2; iWsd = 3; iWsp = 4; iX = 5;
        int off = (n_in >= 12 && in_sizes[6] == 1) ? 1 : 0;
        iMask = 6 + off; iMmap = 7 + off; iTmap = 8 + off; iP = 9 + off; iR = 10 + off;
    } else {
        int seen4096 = 0, seen64000 = 0;
        for (int i = 0; i < n_in; i++) {
            int s = in_sizes[i];
            if      (s == SZ_X)      iX = i;
            else if (s == SZ_MASK)   iMask = i;
            else if (s == SZ_WMDEC)  iWmd = i;
            else if (s == SZ_WMAP)   iWmap = i;
            else if (s == SZ_R)      iR = i;
            else if (s == SZ_TMAP)   iTmap = i;
            else if (s == SZ_MMAP)   iMmap = i;
            else if (s == SZ_WPRIOR) { if (seen4096++ == 0) iWsp = i; else iWmp = i; }
            else if (s == SZ_WSDEC)  { if (seen64000++ == 0) iWsd = i; else iP = i; }
        }
    }

    const float* X    = (const float*)d_in[iX];
    const float* mask = (const float*)d_in[iMask];
    const float* Wsp  = (const float*)d_in[iWsp];
    const float* Wsd  = (const float*)d_in[iWsd];
    const float* Wmp  = (const float*)d_in[iWmp];
    const float* Wmd  = (const float*)d_in[iWmd];
    const float* Wmap = (const float*)d_in[iWmap];
    const float* R    = (const float*)d_in[iR];
    const float* P    = (const float*)d_in[iP];
    const int*   tmap = (const int*)d_in[iTmap];
    const int*   mmap = (const int*)d_in[iMmap];
    float* out = (float*)d_out;

    prep_kernel<<<NB, 256>>>(X, mask, Wsp, Wsd, Wmp, Wmd, Wmap, P, tmap, mmap);

    dim3 ggrid(4, (NITEMS + 127) / 128);
    gemm_mma_kernel<<<ggrid, 256>>>(R);

    knn_select_kernel<<<NB, 256>>>();

    refine_kernel<<<NBLK, 256>>>(R);

    rank_kernel<<<NB, 256>>>();

    fuse_kernel<<<NB, 256>>>(tmap, mmap, out);
}